// round 7
// baseline (speedup 1.0000x reference)
#include <cuda_runtime.h>
#include <stdint.h>

#define SEQ 2048
#define DM  1024
#define NH  16
#define DH  64
#define BATCH 4
#define MROWS 8192

// log2(e)/sqrt(64) folded into Q so softmax uses ex2 directly
#define QSCALE 0.1803368801111204f

// Scratch (device globals: allocation-free), all in mma-fragment-packed layouts
__device__ float g_xpack[(size_t)MROWS * DM];            // x as a-frags
__device__ float g_wpack[4 * (size_t)DM * DM];           // Wq/Wk/Wv/Wo as b-frags
__device__ float g_qpack[(size_t)BATCH * NH * SEQ * DH]; // Q as a-frags (scaled)
__device__ float g_kpack[(size_t)BATCH * NH * SEQ * DH]; // K as S-gemm b-frags
__device__ float g_vpack[(size_t)BATCH * NH * SEQ * DH]; // V as PV-gemm b-frags
__device__ float g_apack[(size_t)MROWS * DM];            // attn out as a-frags

// ---------------------------------------------------------------------------
// helpers
// ---------------------------------------------------------------------------
__device__ __forceinline__ float tf32f(float x) {
    unsigned u; asm("cvt.rna.tf32.f32 %0, %1;" : "=r"(u) : "f"(x));
    return __uint_as_float(u);
}
__device__ __forceinline__ unsigned fu(float x) { return __float_as_uint(x); }
__device__ __forceinline__ float ex2f_(float x) {
    float y; asm("ex2.approx.f32 %0, %1;" : "=f"(y) : "f"(x)); return y;
}
__device__ __forceinline__ float rcpf_(float x) {
    float y; asm("rcp.approx.f32 %0, %1;" : "=f"(y) : "f"(x)); return y;
}
__device__ __forceinline__ void mma8(float* c, const unsigned* a,
                                     unsigned b0, unsigned b1) {
    asm volatile(
        "mma.sync.aligned.m16n8k8.row.col.f32.tf32.tf32.f32 "
        "{%0,%1,%2,%3}, {%4,%5,%6,%7}, {%8,%9}, {%0,%1,%2,%3};"
        : "+f"(c[0]), "+f"(c[1]), "+f"(c[2]), "+f"(c[3])
        : "r"(a[0]), "r"(a[1]), "r"(a[2]), "r"(a[3]), "r"(b0), "r"(b1));
}

// ---------------------------------------------------------------------------
// Pack x into a-fragment layout.
// a-frag (m16n8k8 tf32), lane = gid*4+tig (gid=lane>>2, tig=lane&3):
//   a0=A[gid][tig] a1=A[gid+8][tig] a2=A[gid][tig+4] a3=A[gid+8][tig+4]
// float4 index: (mtile16 * 128 + kstep8) * 32 + lane
// ---------------------------------------------------------------------------
__global__ __launch_bounds__(256) void xpack_kernel(const float* __restrict__ x)
{
    int t = blockIdx.x * 256 + threadIdx.x;      // < 512*128*32
    int lane = t & 31, ks = (t >> 5) & 127, mt = t >> 12;
    int m = mt * 16 + (lane >> 2), k = ks * 8 + (lane & 3);
    const float* xp = x + (size_t)m * DM + k;
    float4 o;
    o.x = tf32f(xp[0]);
    o.y = tf32f(xp[8 * DM]);
    o.z = tf32f(xp[4]);
    o.w = tf32f(xp[8 * DM + 4]);
    ((float4*)g_xpack)[t] = o;
}

// ---------------------------------------------------------------------------
// Pack W into b-fragment layout (2 k-steps per float4).
// b-frag: lane gid = n col, tig = k row: b0=B[tig][gid], b1=B[tig+4][gid]
// float4 index: ((mat*128 + ntile8)*64 + ks4)*32 + lane,
//   .x=W[ks4*16+tig][n] .y=+4 rows .z=+8 .w=+12
// ---------------------------------------------------------------------------
__global__ __launch_bounds__(256) void wpack_kernel(
    const float* __restrict__ Wq, const float* __restrict__ Wk,
    const float* __restrict__ Wv, const float* __restrict__ Wo)
{
    int t = blockIdx.x * 256 + threadIdx.x;      // < 4*128*64*32
    int lane = t & 31, ks4 = (t >> 5) & 63, nt = (t >> 11) & 127, mat = t >> 18;
    const float* W = (mat == 0) ? Wq : (mat == 1) ? Wk : (mat == 2) ? Wv : Wo;
    int n = nt * 8 + (lane >> 2), k = ks4 * 16 + (lane & 3);
    const float* wp = W + (size_t)k * DM + n;
    float4 o;
    o.x = tf32f(wp[0]);
    o.y = tf32f(wp[4 * DM]);
    o.z = tf32f(wp[8 * DM]);
    o.w = tf32f(wp[12 * DM]);
    ((float4*)g_wpack)[t] = o;
}

// ---------------------------------------------------------------------------
// Scatter-store a QKV projection result element (seq s, head-dim d) into the
// fragment-packed layout the attention kernel consumes.
// ---------------------------------------------------------------------------
__device__ __forceinline__ void qkv_store(int mode, int bh, int s, int d, float v)
{
    if (mode == 0) {          // Q a-frags (scaled to log2 domain)
        size_t idx = ((size_t)(bh * 128 + (s >> 4)) * 8 + (d >> 3)) * 128
                   + ((s & 7) * 4 + (d & 3)) * 4 + ((s >> 3) & 1) + 2 * ((d >> 2) & 1);
        g_qpack[idx] = tf32f(v * QSCALE);
    } else if (mode == 1) {   // K as S-gemm b-frags: keytile8, d-group16
        size_t idx = ((size_t)(bh * 256 + (s >> 3)) * 4 + (d >> 4)) * 128
                   + ((s & 7) * 4 + (d & 3)) * 4 + ((d >> 3) & 1) * 2 + ((d >> 2) & 1);
        g_kpack[idx] = tf32f(v);
    } else {                  // V as PV-gemm b-frags: d-tile8, key-group16
        size_t idx = ((size_t)(bh * 8 + (d >> 3)) * 128 + (s >> 4)) * 128
                   + ((d & 7) * 4 + (s & 3)) * 4 + ((s >> 3) & 1) * 2 + ((s >> 2) & 1);
        g_vpack[idx] = tf32f(v);
    }
}

// ---------------------------------------------------------------------------
// Zero-smem GEMM: 128x128 block, 256 threads, 8 warps (2m x 4n), warp 64x32.
// All fragments arrive via LDG.128 from pre-packed global (L2 hits).
// pass 0: QKV (blockIdx.z = mode), A = g_xpack. pass 1: oproj, A = g_apack.
// ---------------------------------------------------------------------------
__global__ __launch_bounds__(256, 2) void gemm_kernel(
    const float* __restrict__ bq, const float* __restrict__ bk,
    const float* __restrict__ bv, const float* __restrict__ bo,
    float* __restrict__ outp, int pass)
{
    const int mode = (pass == 0) ? (int)blockIdx.z : 3;
    const float* Ap   = (pass == 0) ? g_xpack : g_apack;
    const float* Bp   = g_wpack + (size_t)mode * DM * DM;
    const float* bias = (mode == 0) ? bq : (mode == 1) ? bk : (mode == 2) ? bv : bo;
    const int m0 = blockIdx.y * 128, n0 = blockIdx.x * 128;
    const int tid = threadIdx.x, l = tid & 31, w = tid >> 5;
    const int wm = w & 1, wn = w >> 1;
    const int lq = l >> 2, lr = l & 3;

    float acc[4][4][4] = {};

    // float4 bases: a: (mtile*128 + ks)*32 + lane; b: (ntile*64 + ks4)*32 + lane
    const float4* abase = (const float4*)Ap + ((size_t)(m0 >> 4) + wm * 4) * 4096 + l;
    const float4* bbase = (const float4*)Bp + ((size_t)(n0 >> 3) + wn * 4) * 2048 + l;

    for (int ks4 = 0; ks4 < 64; ++ks4) {
        float4 bf[4], a0[4], a1[4];
#pragma unroll
        for (int nt = 0; nt < 4; ++nt)
            bf[nt] = bbase[(size_t)nt * 2048 + ks4 * 32];
#pragma unroll
        for (int mt = 0; mt < 4; ++mt) {
            a0[mt] = abase[(size_t)mt * 4096 + (2 * ks4) * 32];
            a1[mt] = abase[(size_t)mt * 4096 + (2 * ks4 + 1) * 32];
        }
#pragma unroll
        for (int mt = 0; mt < 4; ++mt)
#pragma unroll
            for (int nt = 0; nt < 4; ++nt) {
                mma8(acc[mt][nt], (const unsigned*)&a0[mt], fu(bf[nt].x), fu(bf[nt].y));
                mma8(acc[mt][nt], (const unsigned*)&a1[mt], fu(bf[nt].z), fu(bf[nt].w));
            }
    }

    if (mode == 3) {
#pragma unroll
        for (int mt = 0; mt < 4; ++mt) {
            int mrow = m0 + wm * 64 + mt * 16 + lq;
#pragma unroll
            for (int nt = 0; nt < 4; ++nt) {
                int col = n0 + wn * 32 + nt * 8 + 2 * lr;
                float2 bx = *(const float2*)(bias + col);
                *(float2*)(outp + (size_t)mrow * DM + col) =
                    make_float2(acc[mt][nt][0] + bx.x, acc[mt][nt][1] + bx.y);
                *(float2*)(outp + (size_t)(mrow + 8) * DM + col) =
                    make_float2(acc[mt][nt][2] + bx.x, acc[mt][nt][3] + bx.y);
            }
        }
    } else {
#pragma unroll
        for (int mt = 0; mt < 4; ++mt) {
            int mrow = m0 + wm * 64 + mt * 16 + lq;
            int bb = mrow >> 11, s = mrow & 2047;
#pragma unroll
            for (int nt = 0; nt < 4; ++nt) {
                int col = n0 + wn * 32 + nt * 8 + 2 * lr;
                int bh = bb * 16 + (col >> 6), d = col & 63;
                float b0 = bias[col], b1 = bias[col + 1];
                qkv_store(mode, bh, s,     d,     acc[mt][nt][0] + b0);
                qkv_store(mode, bh, s,     d + 1, acc[mt][nt][1] + b1);
                qkv_store(mode, bh, s + 8, d,     acc[mt][nt][2] + b0);
                qkv_store(mode, bh, s + 8, d + 1, acc[mt][nt][3] + b1);
            }
        }
    }
}

// ---------------------------------------------------------------------------
// Causal flash attention. Block = 128 queries of one (b,h), 8 warps x 16 rows.
// Q a-frags from g_qpack (registers, loaded once). K/V b-frags via direct
// LDG.128 from packed buffers. P round-trips a PER-WARP smem slice: no block
// barriers anywhere in the mainloop.
// ---------------------------------------------------------------------------
__global__ __launch_bounds__(256) void attn_kernel()
{
    __shared__ float Psm[8][16 * 68];
    const int qb  = 15 - blockIdx.x;    // heavy tiles first
    const int bh  = blockIdx.y;
    const int tid = threadIdx.x, w = tid >> 5, l = tid & 31;
    const int lq = l >> 2, lr = l & 3;
    float* P = Psm[w];

    const float4* qf = (const float4*)g_qpack
                     + ((size_t)(bh * 128 + qb * 8 + w) * 8) * 32 + l;
    const float4* kf = (const float4*)g_kpack + ((size_t)bh * 1024) * 32 + l;
    const float4* vf = (const float4*)g_vpack + ((size_t)bh * 1024) * 32 + l;

    float4 qa4[8];
#pragma unroll
    for (int s = 0; s < 8; ++s) qa4[s] = qf[s * 32];

    float m0v = -1e30f, m1v = -1e30f, l0v = 0.0f, l1v = 0.0f;
    float o[8][4] = {};

    const int ktmax = 2 * qb + 1;
    for (int kt = 0; kt <= ktmax; ++kt) {
        // ---- S = Q K^T ----
        float sc[8][4] = {};
#pragma unroll
        for (int sp = 0; sp < 4; ++sp) {
#pragma unroll
            for (int nt = 0; nt < 8; ++nt) {
                float4 b4 = kf[(size_t)((kt * 8 + nt) * 4 + sp) * 32];
                mma8(sc[nt], (const unsigned*)&qa4[2 * sp],     fu(b4.x), fu(b4.y));
                mma8(sc[nt], (const unsigned*)&qa4[2 * sp + 1], fu(b4.z), fu(b4.w));
            }
        }

        // ---- causal mask (last two tiles only) ----
        if (kt >= 2 * qb) {
            int qg0 = qb * 128 + w * 16 + lq, qg1 = qg0 + 8;
#pragma unroll
            for (int nt = 0; nt < 8; ++nt) {
                int kg = kt * 64 + nt * 8 + 2 * lr;
                if (kg > qg0)     sc[nt][0] = -1e30f;
                if (kg + 1 > qg0) sc[nt][1] = -1e30f;
                if (kg > qg1)     sc[nt][2] = -1e30f;
                if (kg + 1 > qg1) sc[nt][3] = -1e30f;
            }
        }

        // ---- online softmax (log2 domain), 2 rows per lane ----
        float mx0 = -1e30f, mx1 = -1e30f;
#pragma unroll
        for (int nt = 0; nt < 8; ++nt) {
            mx0 = fmaxf(mx0, fmaxf(sc[nt][0], sc[nt][1]));
            mx1 = fmaxf(mx1, fmaxf(sc[nt][2], sc[nt][3]));
        }
        mx0 = fmaxf(mx0, __shfl_xor_sync(0xffffffffu, mx0, 1));
        mx0 = fmaxf(mx0, __shfl_xor_sync(0xffffffffu, mx0, 2));
        mx1 = fmaxf(mx1, __shfl_xor_sync(0xffffffffu, mx1, 1));
        mx1 = fmaxf(mx1, __shfl_xor_sync(0xffffffffu, mx1, 2));

        float mn0 = fmaxf(m0v, mx0), mn1 = fmaxf(m1v, mx1);
        float al0 = ex2f_(m0v - mn0), al1 = ex2f_(m1v - mn1);
        m0v = mn0; m1v = mn1;

        float rs0 = 0.0f, rs1 = 0.0f;
#pragma unroll
        for (int nt = 0; nt < 8; ++nt) {
            sc[nt][0] = ex2f_(sc[nt][0] - mn0);
            sc[nt][1] = ex2f_(sc[nt][1] - mn0);
            sc[nt][2] = ex2f_(sc[nt][2] - mn1);
            sc[nt][3] = ex2f_(sc[nt][3] - mn1);
            rs0 += sc[nt][0] + sc[nt][1];
            rs1 += sc[nt][2] + sc[nt][3];
        }
        rs0 += __shfl_xor_sync(0xffffffffu, rs0, 1);
        rs0 += __shfl_xor_sync(0xffffffffu, rs0, 2);
        rs1 += __shfl_xor_sync(0xffffffffu, rs1, 1);
        rs1 += __shfl_xor_sync(0xffffffffu, rs1, 2);
        l0v = l0v * al0 + rs0;
        l1v = l1v * al1 + rs1;
#pragma unroll
        for (int nt = 0; nt < 8; ++nt) {
            o[nt][0] *= al0; o[nt][1] *= al0;
            o[nt][2] *= al1; o[nt][3] *= al1;
        }

        // ---- P c-frag -> per-warp smem -> a-frag (warp-private: no bar) ----
        __syncwarp();
#pragma unroll
        for (int nt = 0; nt < 8; ++nt) {
            *(float2*)&P[lq * 68 + nt * 8 + 2 * lr] =
                make_float2(sc[nt][0], sc[nt][1]);
            *(float2*)&P[(lq + 8) * 68 + nt * 8 + 2 * lr] =
                make_float2(sc[nt][2], sc[nt][3]);
        }
        __syncwarp();

        // ---- O += P V ----
#pragma unroll
        for (int sp = 0; sp < 4; ++sp) {
            unsigned pe[4], po[4];
            pe[0] = fu(P[lq * 68 + 16 * sp + lr]);
            pe[1] = fu(P[(lq + 8) * 68 + 16 * sp + lr]);
            pe[2] = fu(P[lq * 68 + 16 * sp + 4 + lr]);
            pe[3] = fu(P[(lq + 8) * 68 + 16 * sp + 4 + lr]);
            po[0] = fu(P[lq * 68 + 16 * sp + 8 + lr]);
            po[1] = fu(P[(lq + 8) * 68 + 16 * sp + 8 + lr]);
            po[2] = fu(P[lq * 68 + 16 * sp + 12 + lr]);
            po[3] = fu(P[(lq + 8) * 68 + 16 * sp + 12 + lr]);
#pragma unroll
            for (int nt = 0; nt < 8; ++nt) {
                float4 v4 = vf[(size_t)(nt * 128 + kt * 4 + sp) * 32];
                mma8(o[nt], pe, fu(v4.x), fu(v4.y));
                mma8(o[nt], po, fu(v4.z), fu(v4.w));
            }
        }
    }

    // ---- epilogue: normalize, store pre-packed a-frags for oproj ----
    float i0 = rcpf_(l0v), i1 = rcpf_(l1v);
    const int b = bh >> 4, h = bh & 15;
    const size_t mtbase = (size_t)(b * 128 + qb * 8 + w) * 128;
#pragma unroll
    for (int nt = 0; nt < 8; ++nt) {
#pragma unroll
        for (int i = 0; i < 2; ++i) {
            int n = h * 64 + nt * 8 + 2 * lr + i;
            size_t base = (mtbase + (n >> 3)) * 128
                        + (lq * 4 + (n & 3)) * 4 + 2 * ((n >> 2) & 1);
            g_apack[base]     = tf32f(o[nt][i]     * i0);
            g_apack[base + 1] = tf32f(o[nt][2 + i] * i1);
        }
    }
}

// ---------------------------------------------------------------------------
extern "C" void kernel_launch(void* const* d_in, const int* in_sizes, int n_in,
                              void* d_out, int out_size)
{
    const float* x  = (const float*)d_in[0];
    const float* Wq = (const float*)d_in[1];
    const float* bq = (const float*)d_in[2];
    const float* Wk = (const float*)d_in[3];
    const float* bk = (const float*)d_in[4];
    const float* Wv = (const float*)d_in[5];
    const float* bv = (const float*)d_in[6];
    const float* Wo = (const float*)d_in[7];
    const float* bo = (const float*)d_in[8];

    xpack_kernel<<<8192, 256>>>(x);
    wpack_kernel<<<4096, 256>>>(Wq, Wk, Wv, Wo);
    gemm_kernel<<<dim3(8, 64, 3), 256>>>(bq, bk, bv, bo, nullptr, 0);
    attn_kernel<<<dim3(16, 64), 256>>>();
    gemm_kernel<<<dim3(8, 64, 1), 256>>>(bq, bk, bv, bo, (float*)d_out, 1);
}

// round 9
// speedup vs baseline: 2.4370x; 2.4370x over previous
#include <cuda_runtime.h>
#include <stdint.h>

#define SEQ 2048
#define DM  1024
#define NH  16
#define DH  64
#define BATCH 4
#define MROWS 8192

// log2(e)/sqrt(64) folded into Q at projection time
#define QSCALE 0.1803368801111204f

// Scratch (device globals: allocation-free)
__device__ float g_xr[(size_t)MROWS * DM];              // x, tf32-rounded
__device__ float g_wT[4 * (size_t)DM * DM];             // W^T [mat][n][k], rounded
__device__ float g_q[(size_t)BATCH * NH * SEQ * DH];    // scaled+rounded
__device__ float g_k[(size_t)BATCH * NH * SEQ * DH];    // rounded
__device__ float g_v[(size_t)BATCH * NH * SEQ * DH];    // rounded
__device__ float g_attn[(size_t)MROWS * DM];            // rounded

// ---------------------------------------------------------------------------
// helpers
// ---------------------------------------------------------------------------
__device__ __forceinline__ float tf32f(float x) {
    unsigned u; asm("cvt.rna.tf32.f32 %0, %1;" : "=r"(u) : "f"(x));
    return __uint_as_float(u);
}
__device__ __forceinline__ unsigned fu(float x) { return __float_as_uint(x); }
__device__ __forceinline__ float ex2f_(float x) {
    float y; asm("ex2.approx.f32 %0, %1;" : "=f"(y) : "f"(x)); return y;
}
__device__ __forceinline__ float rcpf_(float x) {
    float y; asm("rcp.approx.f32 %0, %1;" : "=f"(y) : "f"(x)); return y;
}
__device__ __forceinline__ uint32_t smem_u32(const void* p) {
    uint32_t a;
    asm("{ .reg .u64 t; cvta.to.shared.u64 t, %1; cvt.u32.u64 %0, t; }"
        : "=r"(a) : "l"(p));
    return a;
}
__device__ __forceinline__ void cpa16(uint32_t dst, const void* src) {
    asm volatile("cp.async.cg.shared.global [%0], [%1], 16;"
                 :: "r"(dst), "l"(src));
}
#define CP_COMMIT() asm volatile("cp.async.commit_group;" ::: "memory")
#define CP_WAIT0()  asm volatile("cp.async.wait_group 0;" ::: "memory")

__device__ __forceinline__ void mma8(float* c, const unsigned* a,
                                     unsigned b0, unsigned b1) {
    asm volatile(
        "mma.sync.aligned.m16n8k8.row.col.f32.tf32.tf32.f32 "
        "{%0,%1,%2,%3}, {%4,%5,%6,%7}, {%8,%9}, {%0,%1,%2,%3};"
        : "+f"(c[0]), "+f"(c[1]), "+f"(c[2]), "+f"(c[3])
        : "r"(a[0]), "r"(a[1]), "r"(a[2]), "r"(a[3]), "r"(b0), "r"(b1));
}

// ---------------------------------------------------------------------------
// prep: round x; transpose+round W
// ---------------------------------------------------------------------------
__global__ __launch_bounds__(256) void xr_kernel(const float* __restrict__ x)
{
    int t = blockIdx.x * 256 + threadIdx.x;        // < 2097152
    float4 v = ((const float4*)x)[t];
    ((float4*)g_xr)[t] = make_float4(tf32f(v.x), tf32f(v.y),
                                     tf32f(v.z), tf32f(v.w));
}

__global__ __launch_bounds__(256) void wtrans_kernel(
    const float* __restrict__ Wq, const float* __restrict__ Wk,
    const float* __restrict__ Wv, const float* __restrict__ Wo)
{
    __shared__ float t[32][33];
    const int mat = blockIdx.z;
    const float* W = (mat == 0) ? Wq : (mat == 1) ? Wk : (mat == 2) ? Wv : Wo;
    const int k0 = blockIdx.x * 32, n0 = blockIdx.y * 32;
    const int tx = threadIdx.x & 31, ty = threadIdx.x >> 5;
#pragma unroll
    for (int i = 0; i < 32; i += 8)
        t[ty + i][tx] = W[(size_t)(k0 + ty + i) * DM + n0 + tx];
    __syncthreads();
    float* o = g_wT + (size_t)mat * DM * DM;
#pragma unroll
    for (int i = 0; i < 32; i += 8)
        o[(size_t)(n0 + ty + i) * DM + k0 + tx] = tf32f(t[tx][ty + i]);
}

// ---------------------------------------------------------------------------
// GEMM: 128x128 block, BK=32, 256 threads, 8 warps (2m x 4n), warp 64x32.
// Both tiles staged natural row-major [row][k] stride 36 (conflict-free
// fragment LDS: bank = 4*lq + lr), cp.async double-buffered, 1 bar/k-block.
// pass 0: QKV (blockIdx.z = mode), A = g_xr. pass 1: oproj, A = g_attn.
// ---------------------------------------------------------------------------
#define GSMEM (2 * 2 * 128 * 36 * 4)      // 73728 B

__global__ __launch_bounds__(256, 2) void gemm_kernel(
    const float* __restrict__ bq, const float* __restrict__ bk,
    const float* __restrict__ bv, const float* __restrict__ bo,
    float* __restrict__ outp, int pass)
{
    extern __shared__ float fsm[];
    const uint32_t sb = smem_u32(fsm);

    const int mode = (pass == 0) ? (int)blockIdx.z : 3;
    const float* Ar   = (pass == 0) ? g_xr : g_attn;
    const float* Br   = g_wT + (size_t)mode * DM * DM;
    const float* bias = (mode == 0) ? bq : (mode == 1) ? bk
                      : (mode == 2) ? bv : bo;
    const int m0 = blockIdx.y * 128, n0 = blockIdx.x * 128;
    const int tid = threadIdx.x, l = tid & 31, w = tid >> 5;
    const int lq = l >> 2, lr = l & 3;
    const int wm = w & 1, wn = w >> 1;

    float acc[4][4][4] = {};

    // prefetch k-block i into buffer (i&1)
    const int c0r = tid >> 3, c0k = tid & 7;   // row/chunk within 256-thread sweep
#define GPF(i)                                                            \
    do {                                                                  \
        const float* As_ = Ar + (size_t)m0 * DM + (i) * 32;               \
        const float* Bs_ = Br + (size_t)n0 * DM + (i) * 32;               \
        uint32_t ab_ = sb + ((i) & 1) * 36864;                            \
        uint32_t bb_ = ab_ + 18432;                                       \
        _Pragma("unroll")                                                 \
        for (int u = 0; u < 4; ++u) {                                     \
            int row = c0r + u * 32;                                       \
            cpa16(ab_ + row * 144 + c0k * 16,                             \
                  As_ + (size_t)row * DM + c0k * 4);                      \
            cpa16(bb_ + row * 144 + c0k * 16,                             \
                  Bs_ + (size_t)row * DM + c0k * 4);                      \
        }                                                                 \
        CP_COMMIT();                                                      \
    } while (0)

    GPF(0);
    for (int i = 0; i < 32; ++i) {
        CP_WAIT0();
        __syncthreads();
        if (i < 31) GPF(i + 1);
        const float* As = fsm + ((i & 1) ? 9216 : 0);
        const float* Bs = As + 4608;
#pragma unroll
        for (int ks = 0; ks < 4; ++ks) {
            const int kk = ks * 8;
            unsigned a[4][4], b[4][2];
#pragma unroll
            for (int mt = 0; mt < 4; ++mt) {
                int row = wm * 64 + mt * 16 + lq;
                a[mt][0] = fu(As[row * 36 + kk + lr]);
                a[mt][1] = fu(As[(row + 8) * 36 + kk + lr]);
                a[mt][2] = fu(As[row * 36 + kk + 4 + lr]);
                a[mt][3] = fu(As[(row + 8) * 36 + kk + 4 + lr]);
            }
#pragma unroll
            for (int nt = 0; nt < 4; ++nt) {
                int col = wn * 32 + nt * 8 + lq;
                b[nt][0] = fu(Bs[col * 36 + kk + lr]);
                b[nt][1] = fu(Bs[col * 36 + kk + 4 + lr]);
            }
#pragma unroll
            for (int mt = 0; mt < 4; ++mt)
#pragma unroll
                for (int nt = 0; nt < 4; ++nt)
                    mma8(acc[mt][nt], a[mt], b[nt][0], b[nt][1]);
        }
    }
#undef GPF

    if (mode == 3) {
#pragma unroll
        for (int mt = 0; mt < 4; ++mt) {
            int mrow = m0 + wm * 64 + mt * 16 + lq;
#pragma unroll
            for (int nt = 0; nt < 4; ++nt) {
                int col = n0 + wn * 32 + nt * 8 + 2 * lr;
                float2 bx = *(const float2*)(bias + col);
                *(float2*)(outp + (size_t)mrow * DM + col) =
                    make_float2(acc[mt][nt][0] + bx.x, acc[mt][nt][1] + bx.y);
                *(float2*)(outp + (size_t)(mrow + 8) * DM + col) =
                    make_float2(acc[mt][nt][2] + bx.x, acc[mt][nt][3] + bx.y);
            }
        }
    } else {
        float* gout = (mode == 0) ? g_q : (mode == 1) ? g_k : g_v;
        const float qs = (mode == 0) ? QSCALE : 1.0f;
#pragma unroll
        for (int mt = 0; mt < 4; ++mt) {
            int mrow = m0 + wm * 64 + mt * 16 + lq;
            int bb = mrow >> 11, s = mrow & 2047;
#pragma unroll
            for (int nt = 0; nt < 4; ++nt) {
                int col = n0 + wn * 32 + nt * 8 + 2 * lr;
                int bh = bb * 16 + (col >> 6), d = col & 63;
                float2 bx = *(const float2*)(bias + col);
                float* op = gout + ((size_t)bh * SEQ + s) * DH + d;
                *(float2*)op =
                    make_float2(tf32f((acc[mt][nt][0] + bx.x) * qs),
                                tf32f((acc[mt][nt][1] + bx.y) * qs));
                *(float2*)(op + 8 * DH) =
                    make_float2(tf32f((acc[mt][nt][2] + bx.x) * qs),
                                tf32f((acc[mt][nt][3] + bx.y) * qs));
            }
        }
    }
}

// ---------------------------------------------------------------------------
// Causal flash attention. Block = 128 queries of one (b,h), 8 warps x 16 rows.
// smem: PQ[128][68] (Q staging -> per-warp P), K double-buf [64][68],
// V double-buf [64][72]. cp.async pipeline, ONE block barrier per kt.
// ---------------------------------------------------------------------------
#define ATTN_SMEM (128 * 68 * 4 + 2 * 64 * 68 * 4 + 2 * 64 * 72 * 4) // 106496

__global__ __launch_bounds__(256) void attn_kernel()
{
    extern __shared__ float sm[];
    const uint32_t sb = smem_u32(sm);
    float* Pq = sm;                                  // [128][68]

    const int qb  = 15 - blockIdx.x;                 // heavy tiles first
    const int bh  = blockIdx.y;
    const int tid = threadIdx.x, w = tid >> 5, l = tid & 31;
    const int lq = l >> 2, lr = l & 3;
    const int r0 = w * 16 + lq;

    const float* qbase = g_q + ((size_t)bh * SEQ + (size_t)qb * 128) * DH;
    const float* kbase = g_k + (size_t)bh * SEQ * DH;
    const float* vbase = g_v + (size_t)bh * SEQ * DH;

    const int cr = tid >> 4, cq = tid & 15;          // 16-row sweep / 16B chunk

#define KVPF(t)                                                           \
    do {                                                                  \
        uint32_t kb_ = sb + 34816 + ((t) & 1) * 17408;                    \
        uint32_t vb_ = sb + 69632 + ((t) & 1) * 18432;                    \
        const float* ks_ = kbase + (size_t)(t) * 64 * DH;                 \
        const float* vs_ = vbase + (size_t)(t) * 64 * DH;                 \
        _Pragma("unroll")                                                 \
        for (int u = 0; u < 4; ++u) {                                     \
            int row = cr + u * 16;                                        \
            cpa16(kb_ + row * 272 + cq * 16, ks_ + row * 64 + cq * 4);    \
            cpa16(vb_ + row * 288 + cq * 16, vs_ + row * 64 + cq * 4);    \
        }                                                                 \
        CP_COMMIT();                                                      \
    } while (0)

    // stage Q (group), prefetch KV tile 0 (group)
#pragma unroll
    for (int u = 0; u < 8; ++u) {
        int c = tid + u * 256, row = c >> 4, q = c & 15;
        cpa16(sb + row * 272 + q * 16, qbase + row * 64 + q * 4);
    }
    CP_COMMIT();
    KVPF(0);
    CP_WAIT0();
    __syncthreads();

    unsigned qa[8][4];
#pragma unroll
    for (int s = 0; s < 8; ++s) {
        qa[s][0] = fu(Pq[r0 * 68 + 8 * s + lr]);
        qa[s][1] = fu(Pq[(r0 + 8) * 68 + 8 * s + lr]);
        qa[s][2] = fu(Pq[r0 * 68 + 8 * s + 4 + lr]);
        qa[s][3] = fu(Pq[(r0 + 8) * 68 + 8 * s + 4 + lr]);
    }

    float m0v = -1e30f, m1v = -1e30f, l0v = 0.0f, l1v = 0.0f;
    float o[8][4] = {};

    const int ktmax = 2 * qb + 1;
    for (int kt = 0; kt <= ktmax; ++kt) {
        if (kt > 0) { CP_WAIT0(); __syncthreads(); }
        if (kt < ktmax) KVPF(kt + 1);

        const float* Ks = sm + 8704 + (kt & 1) * 4352;   // 34816/4, 17408/4
        const float* Vs = sm + 17408 + (kt & 1) * 4608;  // 69632/4, 18432/4

        // ---- S = Q K^T ----
        float sc[8][4] = {};
#pragma unroll
        for (int sp = 0; sp < 8; ++sp)
#pragma unroll
            for (int nt = 0; nt < 8; ++nt) {
                unsigned b0 = fu(Ks[(8 * nt + lq) * 68 + 8 * sp + lr]);
                unsigned b1 = fu(Ks[(8 * nt + lq) * 68 + 8 * sp + 4 + lr]);
                mma8(sc[nt], qa[sp], b0, b1);
            }

        // ---- causal mask (last two tiles only) ----
        if (kt >= 2 * qb) {
            int qg0 = qb * 128 + r0, qg1 = qg0 + 8;
#pragma unroll
            for (int nt = 0; nt < 8; ++nt) {
                int kg = kt * 64 + nt * 8 + 2 * lr;
                if (kg > qg0)     sc[nt][0] = -1e30f;
                if (kg + 1 > qg0) sc[nt][1] = -1e30f;
                if (kg > qg1)     sc[nt][2] = -1e30f;
                if (kg + 1 > qg1) sc[nt][3] = -1e30f;
            }
        }

        // ---- online softmax (log2 domain), 2 rows per lane ----
        float mx0 = -1e30f, mx1 = -1e30f;
#pragma unroll
        for (int nt = 0; nt < 8; ++nt) {
            mx0 = fmaxf(mx0, fmaxf(sc[nt][0], sc[nt][1]));
            mx1 = fmaxf(mx1, fmaxf(sc[nt][2], sc[nt][3]));
        }
        mx0 = fmaxf(mx0, __shfl_xor_sync(0xffffffffu, mx0, 1));
        mx0 = fmaxf(mx0, __shfl_xor_sync(0xffffffffu, mx0, 2));
        mx1 = fmaxf(mx1, __shfl_xor_sync(0xffffffffu, mx1, 1));
        mx1 = fmaxf(mx1, __shfl_xor_sync(0xffffffffu, mx1, 2));

        float mn0 = fmaxf(m0v, mx0), mn1 = fmaxf(m1v, mx1);
        float al0 = ex2f_(m0v - mn0), al1 = ex2f_(m1v - mn1);
        m0v = mn0; m1v = mn1;

        float rs0 = 0.0f, rs1 = 0.0f;
#pragma unroll
        for (int nt = 0; nt < 8; ++nt) {
            sc[nt][0] = ex2f_(sc[nt][0] - mn0);
            sc[nt][1] = ex2f_(sc[nt][1] - mn0);
            sc[nt][2] = ex2f_(sc[nt][2] - mn1);
            sc[nt][3] = ex2f_(sc[nt][3] - mn1);
            rs0 += sc[nt][0] + sc[nt][1];
            rs1 += sc[nt][2] + sc[nt][3];
        }
        rs0 += __shfl_xor_sync(0xffffffffu, rs0, 1);
        rs0 += __shfl_xor_sync(0xffffffffu, rs0, 2);
        rs1 += __shfl_xor_sync(0xffffffffu, rs1, 1);
        rs1 += __shfl_xor_sync(0xffffffffu, rs1, 2);
        l0v = l0v * al0 + rs0;
        l1v = l1v * al1 + rs1;
#pragma unroll
        for (int nt = 0; nt < 8; ++nt) {
            o[nt][0] *= al0; o[nt][1] *= al0;
            o[nt][2] *= al1; o[nt][3] *= al1;
        }

        // ---- P round-trip (warp-private rows: no block barrier) ----
        __syncwarp();
#pragma unroll
        for (int nt = 0; nt < 8; ++nt) {
            *(float2*)&Pq[r0 * 68 + 8 * nt + 2 * lr] =
                make_float2(sc[nt][0], sc[nt][1]);
            *(float2*)&Pq[(r0 + 8) * 68 + 8 * nt + 2 * lr] =
                make_float2(sc[nt][2], sc[nt][3]);
        }
        __syncwarp();

        // ---- O += P V ----
#pragma unroll
        for (int sp = 0; sp < 8; ++sp) {
            unsigned pa[4];
            pa[0] = fu(Pq[r0 * 68 + 8 * sp + lr]);
            pa[1] = fu(Pq[(r0 + 8) * 68 + 8 * sp + lr]);
            pa[2] = fu(Pq[r0 * 68 + 8 * sp + 4 + lr]);
            pa[3] = fu(Pq[(r0 + 8) * 68 + 8 * sp + 4 + lr]);
#pragma unroll
            for (int nt = 0; nt < 8; ++nt) {
                unsigned b0 = fu(Vs[(8 * sp + lr) * 72 + 8 * nt + lq]);
                unsigned b1 = fu(Vs[(8 * sp + 4 + lr) * 72 + 8 * nt + lq]);
                mma8(o[nt], pa, b0, b1);
            }
        }
    }
#undef KVPF

    // ---- epilogue: normalize, tf32-round, store row-major for oproj ----
    float i0 = rcpf_(l0v), i1 = rcpf_(l1v);
    const int b = bh >> 4, h = bh & 15;
    const int q0 = qb * 128 + r0;
#pragma unroll
    for (int nt = 0; nt < 8; ++nt) {
        int d = h * 64 + nt * 8 + 2 * lr;
        *(float2*)(g_attn + ((size_t)b * SEQ + q0) * DM + d) =
            make_float2(tf32f(o[nt][0] * i0), tf32f(o[nt][1] * i0));
        *(float2*)(g_attn + ((size_t)b * SEQ + q0 + 8) * DM + d) =
            make_float2(tf32f(o[nt][2] * i1), tf32f(o[nt][3] * i1));
    }
}

// ---------------------------------------------------------------------------
extern "C" void kernel_launch(void* const* d_in, const int* in_sizes, int n_in,
                              void* d_out, int out_size)
{
    const float* x  = (const float*)d_in[0];
    const float* Wq = (const float*)d_in[1];
    const float* bq = (const float*)d_in[2];
    const float* Wk = (const float*)d_in[3];
    const float* bk = (const float*)d_in[4];
    const float* Wv = (const float*)d_in[5];
    const float* bv = (const float*)d_in[6];
    const float* Wo = (const float*)d_in[7];
    const float* bo = (const float*)d_in[8];

    cudaFuncSetAttribute(gemm_kernel,
                         cudaFuncAttributeMaxDynamicSharedMemorySize, GSMEM);
    cudaFuncSetAttribute(attn_kernel,
                         cudaFuncAttributeMaxDynamicSharedMemorySize, ATTN_SMEM);

    xr_kernel<<<8192, 256>>>(x);
    wtrans_kernel<<<dim3(32, 32, 4), 256>>>(Wq, Wk, Wv, Wo);
    gemm_kernel<<<dim3(8, 64, 3), 256, GSMEM>>>(bq, bk, bv, bo, nullptr, 0);
    attn_kernel<<<dim3(16, 64), 256, ATTN_SMEM>>>();
    gemm_kernel<<<dim3(8, 64, 1), 256, GSMEM>>>(bq, bk, bv, bo,
                                                (float*)d_out, 1);
}

// round 13
// speedup vs baseline: 2.7462x; 1.1269x over previous
#include <cuda_runtime.h>
#include <stdint.h>

#define SEQ 2048
#define DM  1024
#define NH  16
#define DH  64
#define BATCH 4
#define MROWS 8192

// log2(e)/sqrt(64) folded into Q at projection time
#define QSCALE 0.1803368801111204f

// Scratch (device globals: allocation-free), all mma-fragment-packed
__device__ float g_xpack[(size_t)MROWS * DM];            // x as a-frags
__device__ float g_wpack[4 * (size_t)DM * DM];           // W as b-frags
__device__ float g_qpack[(size_t)BATCH * NH * SEQ * DH]; // Q a-frags (scaled)
__device__ float g_kpack[(size_t)BATCH * NH * SEQ * DH]; // K S-gemm b-frags
__device__ float g_vpack[(size_t)BATCH * NH * SEQ * DH]; // V PV-gemm b-frags
__device__ float g_apack[(size_t)MROWS * DM];            // attn out a-frags

// ---------------------------------------------------------------------------
// helpers
// ---------------------------------------------------------------------------
__device__ __forceinline__ float tf32f(float x) {
    unsigned u; asm("cvt.rna.tf32.f32 %0, %1;" : "=r"(u) : "f"(x));
    return __uint_as_float(u);
}
__device__ __forceinline__ unsigned fu(float x) { return __float_as_uint(x); }
__device__ __forceinline__ float ex2f_(float x) {
    float y; asm("ex2.approx.f32 %0, %1;" : "=f"(y) : "f"(x)); return y;
}
__device__ __forceinline__ float rcpf_(float x) {
    float y; asm("rcp.approx.f32 %0, %1;" : "=f"(y) : "f"(x)); return y;
}
__device__ __forceinline__ uint32_t smem_u32(const void* p) {
    uint32_t a;
    asm("{ .reg .u64 t; cvta.to.shared.u64 t, %1; cvt.u32.u64 %0, t; }"
        : "=r"(a) : "l"(p));
    return a;
}
__device__ __forceinline__ void cpa16(uint32_t dst, const void* src) {
    asm volatile("cp.async.cg.shared.global [%0], [%1], 16;"
                 :: "r"(dst), "l"(src));
}
#define CP_COMMIT() asm volatile("cp.async.commit_group;" ::: "memory")
#define CP_WAIT0()  asm volatile("cp.async.wait_group 0;" ::: "memory")

__device__ __forceinline__ void mma8(float* c, const unsigned* a,
                                     unsigned b0, unsigned b1) {
    asm volatile(
        "mma.sync.aligned.m16n8k8.row.col.f32.tf32.tf32.f32 "
        "{%0,%1,%2,%3}, {%4,%5,%6,%7}, {%8,%9}, {%0,%1,%2,%3};"
        : "+f"(c[0]), "+f"(c[1]), "+f"(c[2]), "+f"(c[3])
        : "r"(a[0]), "r"(a[1]), "r"(a[2]), "r"(a[3]), "r"(b0), "r"(b1));
}

// ---------------------------------------------------------------------------
// Pack x into a-frag layout: float4 idx (mtile16*128 + kstep8)*32 + lane
//   .x=A[lq][lr] .y=A[lq+8][lr] .z=A[lq][lr+4] .w=A[lq+8][lr+4]
// ---------------------------------------------------------------------------
__global__ __launch_bounds__(256) void xpack_kernel(const float* __restrict__ x)
{
    int t = blockIdx.x * 256 + threadIdx.x;
    int lane = t & 31, ks = (t >> 5) & 127, mt = t >> 12;
    int m = mt * 16 + (lane >> 2), k = ks * 8 + (lane & 3);
    const float* xp = x + (size_t)m * DM + k;
    ((float4*)g_xpack)[t] = make_float4(tf32f(xp[0]), tf32f(xp[8 * DM]),
                                        tf32f(xp[4]), tf32f(xp[8 * DM + 4]));
}

// ---------------------------------------------------------------------------
// Pack W into b-frag layout: float4 idx ((mat*128 + ntile8)*64 + ks4)*32 + lane
//   (.x,.y) = k-step 2*ks4, (.z,.w) = k-step 2*ks4+1
// ---------------------------------------------------------------------------
__global__ __launch_bounds__(256) void wpack_kernel(
    const float* __restrict__ Wq, const float* __restrict__ Wk,
    const float* __restrict__ Wv, const float* __restrict__ Wo)
{
    int t = blockIdx.x * 256 + threadIdx.x;
    int lane = t & 31, ks4 = (t >> 5) & 63, nt = (t >> 11) & 127, mat = t >> 18;
    const float* W = (mat == 0) ? Wq : (mat == 1) ? Wk : (mat == 2) ? Wv : Wo;
    int n = nt * 8 + (lane >> 2), k = ks4 * 16 + (lane & 3);
    const float* wp = W + (size_t)k * DM + n;
    ((float4*)g_wpack)[t] = make_float4(tf32f(wp[0]), tf32f(wp[4 * DM]),
                                        tf32f(wp[8 * DM]), tf32f(wp[12 * DM]));
}

// ---------------------------------------------------------------------------
// QKV epilogue scatter into packed layouts (verified in R7)
// ---------------------------------------------------------------------------
__device__ __forceinline__ void qkv_store(int mode, int bh, int s, int d, float v)
{
    if (mode == 0) {
        size_t idx = ((size_t)(bh * 128 + (s >> 4)) * 8 + (d >> 3)) * 128
                   + ((s & 7) * 4 + (d & 3)) * 4 + ((s >> 3) & 1) + 2 * ((d >> 2) & 1);
        g_qpack[idx] = tf32f(v * QSCALE);
    } else if (mode == 1) {
        size_t idx = ((size_t)(bh * 256 + (s >> 3)) * 4 + (d >> 4)) * 128
                   + ((s & 7) * 4 + (d & 3)) * 4 + ((d >> 3) & 1) * 2 + ((d >> 2) & 1);
        g_kpack[idx] = tf32f(v);
    } else {
        size_t idx = ((size_t)(bh * 8 + (d >> 3)) * 128 + (s >> 4)) * 128
                   + ((d & 7) * 4 + (s & 3)) * 4 + ((s >> 3) & 1) * 2 + ((s >> 2) & 1);
        g_vpack[idx] = tf32f(v);
    }
}

// ---------------------------------------------------------------------------
// GEMM: 128x128 block, BK=32, 256 threads, 8 warps (2m x 4n), warp 64x32.
// Packed tiles staged via cp.async (linear), fragments via LDS.128.
// smem: per buffer A 16KB + B 16KB, double buffered = 64KB.
// ---------------------------------------------------------------------------
#define GSMEM 65536

__global__ __launch_bounds__(256, 2) void gemm_kernel(
    const float* __restrict__ bq, const float* __restrict__ bk,
    const float* __restrict__ bv, const float* __restrict__ bo,
    float* __restrict__ outp, int pass)
{
    extern __shared__ float fsm[];
    const uint32_t sb = smem_u32(fsm);

    const int mode = (pass == 0) ? (int)blockIdx.z : 3;
    const float* Ap   = (pass == 0) ? g_xpack : g_apack;
    const float* Bp   = g_wpack + (size_t)mode * DM * DM;
    const float* bias = (mode == 0) ? bq : (mode == 1) ? bk
                      : (mode == 2) ? bv : bo;
    const int m0 = blockIdx.y * 128, n0 = blockIdx.x * 128;
    const int tid = threadIdx.x, l = tid & 31, w = tid >> 5;
    const int lq = l >> 2, lr = l & 3;
    const int wm = w & 1, wn = w >> 1;

    float acc[4][4][4] = {};

    // FIXED bases: A tile16 stride = 4096 float4s, B tile8 stride = 2048
    const float4* a4 = (const float4*)Ap + (size_t)(m0 >> 4) * 4096;
    const float4* b4 = (const float4*)Bp + (size_t)(n0 >> 3) * 2048;

#define GPF(i)                                                              \
    do {                                                                    \
        uint32_t base_ = sb + ((i) & 1) * 32768;                            \
        _Pragma("unroll")                                                   \
        for (int u = 0; u < 4; ++u) {                                       \
            int f = tid + u * 256;                                          \
            int mt8 = f >> 7, ks = (f >> 5) & 3, ln = f & 31;               \
            cpa16(base_ + f * 16,                                           \
                  a4 + ((size_t)mt8 * 128 + (i) * 4 + ks) * 32 + ln);       \
            int nt8 = f >> 6, ks4 = (f >> 5) & 1;                           \
            cpa16(base_ + 16384 + f * 16,                                   \
                  b4 + ((size_t)nt8 * 64 + (i) * 2 + ks4) * 32 + ln);       \
        }                                                                   \
        CP_COMMIT();                                                        \
    } while (0)

    GPF(0);
    for (int i = 0; i < 32; ++i) {
        CP_WAIT0();
        __syncthreads();
        if (i < 31) GPF(i + 1);
        const float4* As4 = (const float4*)(fsm + ((i & 1) ? 8192 : 0));
        const float4* Bs4 = As4 + 1024;
#pragma unroll
        for (int ks4 = 0; ks4 < 2; ++ks4) {
            float4 bf[4];
#pragma unroll
            for (int nt = 0; nt < 4; ++nt)
                bf[nt] = Bs4[((wn * 4 + nt) * 2 + ks4) * 32 + l];
#pragma unroll
            for (int h = 0; h < 2; ++h) {
                float4 af[4];
#pragma unroll
                for (int mt = 0; mt < 4; ++mt)
                    af[mt] = As4[((wm * 4 + mt) * 4 + ks4 * 2 + h) * 32 + l];
#pragma unroll
                for (int mt = 0; mt < 4; ++mt)
#pragma unroll
                    for (int nt = 0; nt < 4; ++nt)
                        mma8(acc[mt][nt], (const unsigned*)&af[mt],
                             h ? fu(bf[nt].z) : fu(bf[nt].x),
                             h ? fu(bf[nt].w) : fu(bf[nt].y));
            }
        }
    }
#undef GPF

    if (mode == 3) {
#pragma unroll
        for (int mt = 0; mt < 4; ++mt) {
            int mrow = m0 + wm * 64 + mt * 16 + lq;
#pragma unroll
            for (int nt = 0; nt < 4; ++nt) {
                int col = n0 + wn * 32 + nt * 8 + 2 * lr;
                float2 bx = *(const float2*)(bias + col);
                *(float2*)(outp + (size_t)mrow * DM + col) =
                    make_float2(acc[mt][nt][0] + bx.x, acc[mt][nt][1] + bx.y);
                *(float2*)(outp + (size_t)(mrow + 8) * DM + col) =
                    make_float2(acc[mt][nt][2] + bx.x, acc[mt][nt][3] + bx.y);
            }
        }
    } else {
#pragma unroll
        for (int mt = 0; mt < 4; ++mt) {
            int mrow = m0 + wm * 64 + mt * 16 + lq;
            int bb = mrow >> 11, s = mrow & 2047;
#pragma unroll
            for (int nt = 0; nt < 4; ++nt) {
                int col = n0 + wn * 32 + nt * 8 + 2 * lr;
                int bh = bb * 16 + (col >> 6), d = col & 63;
                float b0 = bias[col], b1 = bias[col + 1];
                qkv_store(mode, bh, s,     d,     acc[mt][nt][0] + b0);
                qkv_store(mode, bh, s,     d + 1, acc[mt][nt][1] + b1);
                qkv_store(mode, bh, s + 8, d,     acc[mt][nt][2] + b0);
                qkv_store(mode, bh, s + 8, d + 1, acc[mt][nt][3] + b1);
            }
        }
    }
}

// ---------------------------------------------------------------------------
// Causal flash attention. Block = 128 queries of one (b,h), 8 warps x 16 rows.
// Packed Q/K/V staged via linear cp.async; fragments via LDS.128.
// smem floats: PQ 8704 (Q stage 8192 -> per-warp P), K 2x4096, V 2x4096.
// ---------------------------------------------------------------------------
#define ATTN_SMEM ((8704 + 8192 + 8192) * 4)   // 100352 B

__global__ __launch_bounds__(256) void attn_kernel()
{
    extern __shared__ float sm[];
    const uint32_t sb = smem_u32(sm);
    float* Pq = sm;

    const int qb  = 15 - blockIdx.x;     // heavy tiles first
    const int bh  = blockIdx.y;
    const int tid = threadIdx.x, w = tid >> 5, l = tid & 31;
    const int lq = l >> 2, lr = l & 3;
    const int r0 = w * 16 + lq;

    const float4* qg = (const float4*)g_qpack + (size_t)(bh * 128 + qb * 8) * 256;
    const float4* kg = (const float4*)g_kpack + (size_t)bh * 32768;
    const float4* vg = (const float4*)g_vpack + (size_t)bh * 32768;

#define KVPF(t)                                                             \
    do {                                                                    \
        uint32_t kb_ = sb + 34816 + ((t) & 1) * 16384;                      \
        uint32_t vb_ = sb + 67584 + ((t) & 1) * 16384;                      \
        _Pragma("unroll")                                                   \
        for (int u = 0; u < 4; ++u) {                                       \
            int f = tid + u * 256;                                          \
            cpa16(kb_ + f * 16, kg + (size_t)(t) * 1024 + f);               \
            cpa16(vb_ + f * 16,                                             \
                  vg + ((size_t)(f >> 7) * 4096 + (t) * 128 + (f & 127)));  \
        }                                                                   \
        CP_COMMIT();                                                        \
    } while (0)

    // stage Q (2048 float4s, linear) + prefetch KV tile 0
#pragma unroll
    for (int u = 0; u < 8; ++u) {
        int f = tid + u * 256;
        cpa16(sb + f * 16, qg + f);
    }
    CP_COMMIT();
    KVPF(0);
    CP_WAIT0();
    __syncthreads();

    const float4* Pq4 = (const float4*)Pq;
    float4 qa4[8];
#pragma unroll
    for (int s = 0; s < 8; ++s) qa4[s] = Pq4[(w * 8 + s) * 32 + l];
    __syncthreads();   // all warps own their Q regs before P overwrites region

    float m0v = -1e30f, m1v = -1e30f, l0v = 0.0f, l1v = 0.0f;
    float o[8][4] = {};

    const int ktmax = 2 * qb + 1;
    for (int kt = 0; kt <= ktmax; ++kt) {
        if (kt > 0) { CP_WAIT0(); __syncthreads(); }
        if (kt < ktmax) KVPF(kt + 1);

        const float4* Ks4 = (const float4*)(sm + 8704 + (kt & 1) * 4096);
        const float4* Vs4 = (const float4*)(sm + 16896 + (kt & 1) * 4096);

        // ---- S = Q K^T : 32 LDS.128 + 64 mma ----
        float sc[8][4] = {};
#pragma unroll
        for (int sp = 0; sp < 4; ++sp)
#pragma unroll
            for (int nt = 0; nt < 8; ++nt) {
                float4 b4 = Ks4[(nt * 4 + sp) * 32 + l];
                mma8(sc[nt], (const unsigned*)&qa4[2 * sp],     fu(b4.x), fu(b4.y));
                mma8(sc[nt], (const unsigned*)&qa4[2 * sp + 1], fu(b4.z), fu(b4.w));
            }

        // ---- causal mask (last two tiles only) ----
        if (kt >= 2 * qb) {
            int qg0 = qb * 128 + r0, qg1 = qg0 + 8;
#pragma unroll
            for (int nt = 0; nt < 8; ++nt) {
                int kg2 = kt * 64 + nt * 8 + 2 * lr;
                if (kg2 > qg0)     sc[nt][0] = -1e30f;
                if (kg2 + 1 > qg0) sc[nt][1] = -1e30f;
                if (kg2 > qg1)     sc[nt][2] = -1e30f;
                if (kg2 + 1 > qg1) sc[nt][3] = -1e30f;
            }
        }

        // ---- online softmax (log2 domain), 2 rows per lane ----
        float mx0 = -1e30f, mx1 = -1e30f;
#pragma unroll
        for (int nt = 0; nt < 8; ++nt) {
            mx0 = fmaxf(mx0, fmaxf(sc[nt][0], sc[nt][1]));
            mx1 = fmaxf(mx1, fmaxf(sc[nt][2], sc[nt][3]));
        }
        mx0 = fmaxf(mx0, __shfl_xor_sync(0xffffffffu, mx0, 1));
        mx0 = fmaxf(mx0, __shfl_xor_sync(0xffffffffu, mx0, 2));
        mx1 = fmaxf(mx1, __shfl_xor_sync(0xffffffffu, mx1, 1));
        mx1 = fmaxf(mx1, __shfl_xor_sync(0xffffffffu, mx1, 2));

        float mn0 = fmaxf(m0v, mx0), mn1 = fmaxf(m1v, mx1);
        float al0 = ex2f_(m0v - mn0), al1 = ex2f_(m1v - mn1);
        m0v = mn0; m1v = mn1;

        float rs0 = 0.0f, rs1 = 0.0f;
#pragma unroll
        for (int nt = 0; nt < 8; ++nt) {
            sc[nt][0] = ex2f_(sc[nt][0] - mn0);
            sc[nt][1] = ex2f_(sc[nt][1] - mn0);
            sc[nt][2] = ex2f_(sc[nt][2] - mn1);
            sc[nt][3] = ex2f_(sc[nt][3] - mn1);
            rs0 += sc[nt][0] + sc[nt][1];
            rs1 += sc[nt][2] + sc[nt][3];
        }
        rs0 += __shfl_xor_sync(0xffffffffu, rs0, 1);
        rs0 += __shfl_xor_sync(0xffffffffu, rs0, 2);
        rs1 += __shfl_xor_sync(0xffffffffu, rs1, 1);
        rs1 += __shfl_xor_sync(0xffffffffu, rs1, 2);
        l0v = l0v * al0 + rs0;
        l1v = l1v * al1 + rs1;
#pragma unroll
        for (int nt = 0; nt < 8; ++nt) {
            o[nt][0] *= al0; o[nt][1] *= al0;
            o[nt][2] *= al1; o[nt][3] *= al1;
        }

        // ---- P round-trip (warp-private rows: no block barrier) ----
        __syncwarp();
#pragma unroll
        for (int nt = 0; nt < 8; ++nt) {
            *(float2*)&Pq[r0 * 68 + 8 * nt + 2 * lr] =
                make_float2(sc[nt][0], sc[nt][1]);
            *(float2*)&Pq[(r0 + 8) * 68 + 8 * nt + 2 * lr] =
                make_float2(sc[nt][2], sc[nt][3]);
        }
        __syncwarp();

        // ---- O += P V : 32 LDS.128 (V) + 64 mma ----
#pragma unroll
        for (int sp = 0; sp < 4; ++sp) {
            unsigned pe[4], po[4];
            pe[0] = fu(Pq[r0 * 68 + 16 * sp + lr]);
            pe[1] = fu(Pq[(r0 + 8) * 68 + 16 * sp + lr]);
            pe[2] = fu(Pq[r0 * 68 + 16 * sp + 4 + lr]);
            pe[3] = fu(Pq[(r0 + 8) * 68 + 16 * sp + 4 + lr]);
            po[0] = fu(Pq[r0 * 68 + 16 * sp + 8 + lr]);
            po[1] = fu(Pq[(r0 + 8) * 68 + 16 * sp + 8 + lr]);
            po[2] = fu(Pq[r0 * 68 + 16 * sp + 12 + lr]);
            po[3] = fu(Pq[(r0 + 8) * 68 + 16 * sp + 12 + lr]);
#pragma unroll
            for (int nt = 0; nt < 8; ++nt) {
                float4 v4 = Vs4[(nt * 4 + sp) * 32 + l];
                mma8(o[nt], pe, fu(v4.x), fu(v4.y));
                mma8(o[nt], po, fu(v4.z), fu(v4.w));
            }
        }
    }
#undef KVPF

    // ---- epilogue: normalize, store a-frag-packed for oproj ----
    float i0 = rcpf_(l0v), i1 = rcpf_(l1v);
    const int b = bh >> 4, h = bh & 15;
    const size_t mtbase = (size_t)(b * 128 + qb * 8 + w) * 128;
#pragma unroll
    for (int nt = 0; nt < 8; ++nt) {
#pragma unroll
        for (int i = 0; i < 2; ++i) {
            int n = h * 64 + nt * 8 + 2 * lr + i;
            size_t base = (mtbase + (n >> 3)) * 128
                        + (lq * 4 + (n & 3)) * 4 + 2 * ((n >> 2) & 1);
            g_apack[base]     = tf32f(o[nt][i]     * i0);
            g_apack[base + 1] = tf32f(o[nt][2 + i] * i1);
        }
    }
}

// ---------------------------------------------------------------------------
extern "C" void kernel_launch(void* const* d_in, const int* in_sizes, int n_in,
                              void* d_out, int out_size)
{
    const float* x  = (const float*)d_in[0];
    const float* Wq = (const float*)d_in[1];
    const float* bq = (const float*)d_in[2];
    const float* Wk = (const float*)d_in[3];
    const float* bk = (const float*)d_in[4];
    const float* Wv = (const float*)d_in[5];
    const float* bv = (const float*)d_in[6];
    const float* Wo = (const float*)d_in[7];
    const float* bo = (const float*)d_in[8];

    cudaFuncSetAttribute(gemm_kernel,
                         cudaFuncAttributeMaxDynamicSharedMemorySize, GSMEM);
    cudaFuncSetAttribute(attn_kernel,
                         cudaFuncAttributeMaxDynamicSharedMemorySize, ATTN_SMEM);

    xpack_kernel<<<8192, 256>>>(x);
    wpack_kernel<<<4096, 256>>>(Wq, Wk, Wv, Wo);
    gemm_kernel<<<dim3(8, 64, 3), 256, GSMEM>>>(bq, bk, bv, bo, nullptr, 0);
    attn_kernel<<<dim3(16, 64), 256, ATTN_SMEM>>>();
    gemm_kernel<<<dim3(8, 64, 1), 256, GSMEM>>>(bq, bk, bv, bo,
                                                (float*)d_out, 1);
}

// round 14
// speedup vs baseline: 2.9277x; 1.0661x over previous
#include <cuda_runtime.h>
#include <stdint.h>

#define SEQ 2048
#define DM  1024
#define NH  16
#define DH  64
#define BATCH 4
#define MROWS 8192

// log2(e)/sqrt(64) folded into Q at projection time
#define QSCALE 0.1803368801111204f

// Scratch (device globals: allocation-free), all mma-fragment-packed
__device__ float g_xpack[(size_t)MROWS * DM];            // x as a-frags
__device__ float g_wpack[4 * (size_t)DM * DM];           // W as b-frags
__device__ float g_qpack[(size_t)BATCH * NH * SEQ * DH]; // Q a-frags (scaled)
__device__ float g_kpack[(size_t)BATCH * NH * SEQ * DH]; // K S-gemm b-frags
__device__ float g_vpack[(size_t)BATCH * NH * SEQ * DH]; // V PV-gemm b-frags
__device__ float g_apack[(size_t)MROWS * DM];            // attn out a-frags

// ---------------------------------------------------------------------------
// helpers
// ---------------------------------------------------------------------------
__device__ __forceinline__ float tf32f(float x) {
    unsigned u; asm("cvt.rna.tf32.f32 %0, %1;" : "=r"(u) : "f"(x));
    return __uint_as_float(u);
}
__device__ __forceinline__ unsigned fu(float x) { return __float_as_uint(x); }
__device__ __forceinline__ float ex2f_(float x) {
    float y; asm("ex2.approx.f32 %0, %1;" : "=f"(y) : "f"(x)); return y;
}
__device__ __forceinline__ float rcpf_(float x) {
    float y; asm("rcp.approx.f32 %0, %1;" : "=f"(y) : "f"(x)); return y;
}
__device__ __forceinline__ uint32_t smem_u32(const void* p) {
    uint32_t a;
    asm("{ .reg .u64 t; cvta.to.shared.u64 t, %1; cvt.u32.u64 %0, t; }"
        : "=r"(a) : "l"(p));
    return a;
}
__device__ __forceinline__ void cpa16(uint32_t dst, const void* src) {
    asm volatile("cp.async.cg.shared.global [%0], [%1], 16;"
                 :: "r"(dst), "l"(src));
}
#define CP_COMMIT() asm volatile("cp.async.commit_group;" ::: "memory")
#define CP_WAIT0()  asm volatile("cp.async.wait_group 0;" ::: "memory")

__device__ __forceinline__ void mma8(float* c, const unsigned* a,
                                     unsigned b0, unsigned b1) {
    asm volatile(
        "mma.sync.aligned.m16n8k8.row.col.f32.tf32.tf32.f32 "
        "{%0,%1,%2,%3}, {%4,%5,%6,%7}, {%8,%9}, {%0,%1,%2,%3};"
        : "+f"(c[0]), "+f"(c[1]), "+f"(c[2]), "+f"(c[3])
        : "r"(a[0]), "r"(a[1]), "r"(a[2]), "r"(a[3]), "r"(b0), "r"(b1));
}

// ---------------------------------------------------------------------------
// Pack x into a-frag layout: float4 idx (mtile16*128 + kstep8)*32 + lane
// ---------------------------------------------------------------------------
__global__ __launch_bounds__(256) void xpack_kernel(const float* __restrict__ x)
{
    int t = blockIdx.x * 256 + threadIdx.x;
    int lane = t & 31, ks = (t >> 5) & 127, mt = t >> 12;
    int m = mt * 16 + (lane >> 2), k = ks * 8 + (lane & 3);
    const float* xp = x + (size_t)m * DM + k;
    ((float4*)g_xpack)[t] = make_float4(tf32f(xp[0]), tf32f(xp[8 * DM]),
                                        tf32f(xp[4]), tf32f(xp[8 * DM + 4]));
}

// ---------------------------------------------------------------------------
// Pack W into b-frag layout: float4 idx ((mat*128 + ntile8)*64 + ks4)*32 + lane
// ---------------------------------------------------------------------------
__global__ __launch_bounds__(256) void wpack_kernel(
    const float* __restrict__ Wq, const float* __restrict__ Wk,
    const float* __restrict__ Wv, const float* __restrict__ Wo)
{
    int t = blockIdx.x * 256 + threadIdx.x;
    int lane = t & 31, ks4 = (t >> 5) & 63, nt = (t >> 11) & 127, mat = t >> 18;
    const float* W = (mat == 0) ? Wq : (mat == 1) ? Wk : (mat == 2) ? Wv : Wo;
    int n = nt * 8 + (lane >> 2), k = ks4 * 16 + (lane & 3);
    const float* wp = W + (size_t)k * DM + n;
    ((float4*)g_wpack)[t] = make_float4(tf32f(wp[0]), tf32f(wp[4 * DM]),
                                        tf32f(wp[8 * DM]), tf32f(wp[12 * DM]));
}

// ---------------------------------------------------------------------------
// QKV epilogue scatter into packed layouts (verified in R7/R13)
// ---------------------------------------------------------------------------
__device__ __forceinline__ void qkv_store(int mode, int bh, int s, int d, float v)
{
    if (mode == 0) {
        size_t idx = ((size_t)(bh * 128 + (s >> 4)) * 8 + (d >> 3)) * 128
                   + ((s & 7) * 4 + (d & 3)) * 4 + ((s >> 3) & 1) + 2 * ((d >> 2) & 1);
        g_qpack[idx] = tf32f(v * QSCALE);
    } else if (mode == 1) {
        size_t idx = ((size_t)(bh * 256 + (s >> 3)) * 4 + (d >> 4)) * 128
                   + ((s & 7) * 4 + (d & 3)) * 4 + ((d >> 3) & 1) * 2 + ((d >> 2) & 1);
        g_kpack[idx] = tf32f(v);
    } else {
        size_t idx = ((size_t)(bh * 8 + (d >> 3)) * 128 + (s >> 4)) * 128
                   + ((d & 7) * 4 + (s & 3)) * 4 + ((s >> 3) & 1) * 2 + ((s >> 2) & 1);
        g_vpack[idx] = tf32f(v);
    }
}

// ---------------------------------------------------------------------------
// GEMM: 128x128 block, BK=32, 256 threads, 8 warps (2m x 4n), warp 64x32.
// Packed tiles staged via cp.async (linear), fragments via LDS.128.
// ---------------------------------------------------------------------------
#define GSMEM 65536

__global__ __launch_bounds__(256, 2) void gemm_kernel(
    const float* __restrict__ bq, const float* __restrict__ bk,
    const float* __restrict__ bv, const float* __restrict__ bo,
    float* __restrict__ outp, int pass)
{
    extern __shared__ float fsm[];
    const uint32_t sb = smem_u32(fsm);

    const int mode = (pass == 0) ? (int)blockIdx.z : 3;
    const float* Ap   = (pass == 0) ? g_xpack : g_apack;
    const float* Bp   = g_wpack + (size_t)mode * DM * DM;
    const float* bias = (mode == 0) ? bq : (mode == 1) ? bk
                      : (mode == 2) ? bv : bo;
    const int m0 = blockIdx.y * 128, n0 = blockIdx.x * 128;
    const int tid = threadIdx.x, l = tid & 31, w = tid >> 5;
    const int lq = l >> 2, lr = l & 3;
    const int wm = w & 1, wn = w >> 1;

    float acc[4][4][4] = {};

    const float4* a4 = (const float4*)Ap + (size_t)(m0 >> 4) * 4096;
    const float4* b4 = (const float4*)Bp + (size_t)(n0 >> 3) * 2048;

#define GPF(i)                                                              \
    do {                                                                    \
        uint32_t base_ = sb + ((i) & 1) * 32768;                            \
        _Pragma("unroll")                                                   \
        for (int u = 0; u < 4; ++u) {                                       \
            int f = tid + u * 256;                                          \
            int mt8 = f >> 7, ks = (f >> 5) & 3, ln = f & 31;               \
            cpa16(base_ + f * 16,                                           \
                  a4 + ((size_t)mt8 * 128 + (i) * 4 + ks) * 32 + ln);       \
            int nt8 = f >> 6, ks4 = (f >> 5) & 1;                           \
            cpa16(base_ + 16384 + f * 16,                                   \
                  b4 + ((size_t)nt8 * 64 + (i) * 2 + ks4) * 32 + ln);       \
        }                                                                   \
        CP_COMMIT();                                                        \
    } while (0)

    GPF(0);
    for (int i = 0; i < 32; ++i) {
        CP_WAIT0();
        __syncthreads();
        if (i < 31) GPF(i + 1);
        const float4* As4 = (const float4*)(fsm + ((i & 1) ? 8192 : 0));
        const float4* Bs4 = As4 + 1024;
#pragma unroll
        for (int ks4 = 0; ks4 < 2; ++ks4) {
            float4 bf[4];
#pragma unroll
            for (int nt = 0; nt < 4; ++nt)
                bf[nt] = Bs4[((wn * 4 + nt) * 2 + ks4) * 32 + l];
#pragma unroll
            for (int h = 0; h < 2; ++h) {
                float4 af[4];
#pragma unroll
                for (int mt = 0; mt < 4; ++mt)
                    af[mt] = As4[((wm * 4 + mt) * 4 + ks4 * 2 + h) * 32 + l];
#pragma unroll
                for (int mt = 0; mt < 4; ++mt)
#pragma unroll
                    for (int nt = 0; nt < 4; ++nt)
                        mma8(acc[mt][nt], (const unsigned*)&af[mt],
                             h ? fu(bf[nt].z) : fu(bf[nt].x),
                             h ? fu(bf[nt].w) : fu(bf[nt].y));
            }
        }
    }
#undef GPF

    if (mode == 3) {
#pragma unroll
        for (int mt = 0; mt < 4; ++mt) {
            int mrow = m0 + wm * 64 + mt * 16 + lq;
#pragma unroll
            for (int nt = 0; nt < 4; ++nt) {
                int col = n0 + wn * 32 + nt * 8 + 2 * lr;
                float2 bx = *(const float2*)(bias + col);
                *(float2*)(outp + (size_t)mrow * DM + col) =
                    make_float2(acc[mt][nt][0] + bx.x, acc[mt][nt][1] + bx.y);
                *(float2*)(outp + (size_t)(mrow + 8) * DM + col) =
                    make_float2(acc[mt][nt][2] + bx.x, acc[mt][nt][3] + bx.y);
            }
        }
    } else {
#pragma unroll
        for (int mt = 0; mt < 4; ++mt) {
            int mrow = m0 + wm * 64 + mt * 16 + lq;
            int bb = mrow >> 11, s = mrow & 2047;
#pragma unroll
            for (int nt = 0; nt < 4; ++nt) {
                int col = n0 + wn * 32 + nt * 8 + 2 * lr;
                int bh = bb * 16 + (col >> 6), d = col & 63;
                float b0 = bias[col], b1 = bias[col + 1];
                qkv_store(mode, bh, s,     d,     acc[mt][nt][0] + b0);
                qkv_store(mode, bh, s,     d + 1, acc[mt][nt][1] + b1);
                qkv_store(mode, bh, s + 8, d,     acc[mt][nt][2] + b0);
                qkv_store(mode, bh, s + 8, d + 1, acc[mt][nt][3] + b1);
            }
        }
    }
}

// ---------------------------------------------------------------------------
// Causal flash attention. Block = 128 queries of one (b,h), 8 warps x 16 rows.
// __launch_bounds__(256,2): cap regs at 128 so 2 blocks/SM coexist
// (2 x 100352B smem = 200704 <= 228KB). Q fragments via direct LDG.128 from
// the packed layout (bit-identical to staged reads). K/V cp.async double-buf.
// ---------------------------------------------------------------------------
#define ATTN_SMEM ((8704 + 8192 + 8192) * 4)   // 100352 B

__global__ __launch_bounds__(256, 2) void attn_kernel()
{
    extern __shared__ float sm[];
    const uint32_t sb = smem_u32(sm);
    float* Pq = sm;                        // P region [128][68]

    const int qb  = 15 - blockIdx.x;       // heavy tiles first
    const int bh  = blockIdx.y;
    const int tid = threadIdx.x, w = tid >> 5, l = tid & 31;
    const int lq = l >> 2, lr = l & 3;
    const int r0 = w * 16 + lq;

    const float4* qg = (const float4*)g_qpack + (size_t)(bh * 128 + qb * 8) * 256;
    const float4* kg = (const float4*)g_kpack + (size_t)bh * 32768;
    const float4* vg = (const float4*)g_vpack + (size_t)bh * 32768;

#define KVPF(t)                                                             \
    do {                                                                    \
        uint32_t kb_ = sb + 34816 + ((t) & 1) * 16384;                      \
        uint32_t vb_ = sb + 67584 + ((t) & 1) * 16384;                      \
        _Pragma("unroll")                                                   \
        for (int u = 0; u < 4; ++u) {                                       \
            int f = tid + u * 256;                                          \
            cpa16(kb_ + f * 16, kg + (size_t)(t) * 1024 + f);               \
            cpa16(vb_ + f * 16,                                             \
                  vg + ((size_t)(f >> 7) * 4096 + (t) * 128 + (f & 127)));  \
        }                                                                   \
        CP_COMMIT();                                                        \
    } while (0)

    KVPF(0);

    // Q fragments straight from packed global (identical bits to staged path)
    float4 qa4[8];
#pragma unroll
    for (int s = 0; s < 8; ++s) qa4[s] = qg[(w * 8 + s) * 32 + l];

    CP_WAIT0();
    __syncthreads();

    float m0v = -1e30f, m1v = -1e30f, l0v = 0.0f, l1v = 0.0f;
    float o[8][4] = {};

    const int ktmax = 2 * qb + 1;
    for (int kt = 0; kt <= ktmax; ++kt) {
        if (kt > 0) { CP_WAIT0(); __syncthreads(); }
        if (kt < ktmax) KVPF(kt + 1);

        const float4* Ks4 = (const float4*)(sm + 8704 + (kt & 1) * 4096);
        const float4* Vs4 = (const float4*)(sm + 16896 + (kt & 1) * 4096);

        // ---- S = Q K^T : 32 LDS.128 + 64 mma ----
        float sc[8][4] = {};
#pragma unroll
        for (int sp = 0; sp < 4; ++sp)
#pragma unroll
            for (int nt = 0; nt < 8; ++nt) {
                float4 b4 = Ks4[(nt * 4 + sp) * 32 + l];
                mma8(sc[nt], (const unsigned*)&qa4[2 * sp],     fu(b4.x), fu(b4.y));
                mma8(sc[nt], (const unsigned*)&qa4[2 * sp + 1], fu(b4.z), fu(b4.w));
            }

        // ---- causal mask (last two tiles only) ----
        if (kt >= 2 * qb) {
            int qg0 = qb * 128 + r0, qg1 = qg0 + 8;
#pragma unroll
            for (int nt = 0; nt < 8; ++nt) {
                int kg2 = kt * 64 + nt * 8 + 2 * lr;
                if (kg2 > qg0)     sc[nt][0] = -1e30f;
                if (kg2 + 1 > qg0) sc[nt][1] = -1e30f;
                if (kg2 > qg1)     sc[nt][2] = -1e30f;
                if (kg2 + 1 > qg1) sc[nt][3] = -1e30f;
            }
        }

        // ---- online softmax (log2 domain), 2 rows per lane ----
        float mx0 = -1e30f, mx1 = -1e30f;
#pragma unroll
        for (int nt = 0; nt < 8; ++nt) {
            mx0 = fmaxf(mx0, fmaxf(sc[nt][0], sc[nt][1]));
            mx1 = fmaxf(mx1, fmaxf(sc[nt][2], sc[nt][3]));
        }
        mx0 = fmaxf(mx0, __shfl_xor_sync(0xffffffffu, mx0, 1));
        mx0 = fmaxf(mx0, __shfl_xor_sync(0xffffffffu, mx0, 2));
        mx1 = fmaxf(mx1, __shfl_xor_sync(0xffffffffu, mx1, 1));
        mx1 = fmaxf(mx1, __shfl_xor_sync(0xffffffffu, mx1, 2));

        float mn0 = fmaxf(m0v, mx0), mn1 = fmaxf(m1v, mx1);
        float al0 = ex2f_(m0v - mn0), al1 = ex2f_(m1v - mn1);
        m0v = mn0; m1v = mn1;

        float rs0 = 0.0f, rs1 = 0.0f;
#pragma unroll
        for (int nt = 0; nt < 8; ++nt) {
            sc[nt][0] = ex2f_(sc[nt][0] - mn0);
            sc[nt][1] = ex2f_(sc[nt][1] - mn0);
            sc[nt][2] = ex2f_(sc[nt][2] - mn1);
            sc[nt][3] = ex2f_(sc[nt][3] - mn1);
            rs0 += sc[nt][0] + sc[nt][1];
            rs1 += sc[nt][2] + sc[nt][3];
        }
        rs0 += __shfl_xor_sync(0xffffffffu, rs0, 1);
        rs0 += __shfl_xor_sync(0xffffffffu, rs0, 2);
        rs1 += __shfl_xor_sync(0xffffffffu, rs1, 1);
        rs1 += __shfl_xor_sync(0xffffffffu, rs1, 2);
        l0v = l0v * al0 + rs0;
        l1v = l1v * al1 + rs1;
#pragma unroll
        for (int nt = 0; nt < 8; ++nt) {
            o[nt][0] *= al0; o[nt][1] *= al0;
            o[nt][2] *= al1; o[nt][3] *= al1;
        }

        // ---- P round-trip (warp-private rows: no block barrier) ----
        __syncwarp();
#pragma unroll
        for (int nt = 0; nt < 8; ++nt) {
            *(float2*)&Pq[r0 * 68 + 8 * nt + 2 * lr] =
                make_float2(sc[nt][0], sc[nt][1]);
            *(float2*)&Pq[(r0 + 8) * 68 + 8 * nt + 2 * lr] =
                make_float2(sc[nt][2], sc[nt][3]);
        }
        __syncwarp();

        // ---- O += P V : 32 LDS.128 (V) + 64 mma ----
#pragma unroll
        for (int sp = 0; sp < 4; ++sp) {
            unsigned pe[4], po[4];
            pe[0] = fu(Pq[r0 * 68 + 16 * sp + lr]);
            pe[1] = fu(Pq[(r0 + 8) * 68 + 16 * sp + lr]);
            pe[2] = fu(Pq[r0 * 68 + 16 * sp + 4 + lr]);
            pe[3] = fu(Pq[(r0 + 8) * 68 + 16 * sp + 4 + lr]);
            po[0] = fu(Pq[r0 * 68 + 16 * sp + 8 + lr]);
            po[1] = fu(Pq[(r0 + 8) * 68 + 16 * sp + 8 + lr]);
            po[2] = fu(Pq[r0 * 68 + 16 * sp + 12 + lr]);
            po[3] = fu(Pq[(r0 + 8) * 68 + 16 * sp + 12 + lr]);
#pragma unroll
            for (int nt = 0; nt < 8; ++nt) {
                float4 v4 = Vs4[(nt * 4 + sp) * 32 + l];
                mma8(o[nt], pe, fu(v4.x), fu(v4.y));
                mma8(o[nt], po, fu(v4.z), fu(v4.w));
            }
        }
    }
#undef KVPF

    // ---- epilogue: normalize, store a-frag-packed for oproj ----
    float i0 = rcpf_(l0v), i1 = rcpf_(l1v);
    const int b = bh >> 4, h = bh & 15;
    const size_t mtbase = (size_t)(b * 128 + qb * 8 + w) * 128;
#pragma unroll
    for (int nt = 0; nt < 8; ++nt) {
#pragma unroll
        for (int i = 0; i < 2; ++i) {
            int n = h * 64 + nt * 8 + 2 * lr + i;
            size_t base = (mtbase + (n >> 3)) * 128
                        + (lq * 4 + (n & 3)) * 4 + 2 * ((n >> 2) & 1);
            g_apack[base]     = tf32f(o[nt][i]     * i0);
            g_apack[base + 1] = tf32f(o[nt][2 + i] * i1);
        }
    }
}

// ---------------------------------------------------------------------------
extern "C" void kernel_launch(void* const* d_in, const int* in_sizes, int n_in,
                              void* d_out, int out_size)
{
    const float* x  = (const float*)d_in[0];
    const float* Wq = (const float*)d_in[1];
    const float* bq = (const float*)d_in[2];
    const float* Wk = (const float*)d_in[3];
    const float* bk = (const float*)d_in[4];
    const float* Wv = (const float*)d_in[5];
    const float* bv = (const float*)d_in[6];
    const float* Wo = (const float*)d_in[7];
    const float* bo = (const float*)d_in[8];

    cudaFuncSetAttribute(gemm_kernel,
                         cudaFuncAttributeMaxDynamicSharedMemorySize, GSMEM);
    cudaFuncSetAttribute(attn_kernel,
                         cudaFuncAttributeMaxDynamicSharedMemorySize, ATTN_SMEM);
    cudaFuncSetAttribute(attn_kernel,
                         cudaFuncAttributePreferredSharedMemoryCarveout, 100);

    xpack_kernel<<<8192, 256>>>(x);
    wpack_kernel<<<4096, 256>>>(Wq, Wk, Wv, Wo);
    gemm_kernel<<<dim3(8, 64, 3), 256, GSMEM>>>(bq, bk, bv, bo, nullptr, 0);
    attn_kernel<<<dim3(16, 64), 256, ATTN_SMEM>>>();
    gemm_kernel<<<dim3(8, 64, 1), 256, GSMEM>>>(bq, bk, bv, bo,
                                                (float*)d_out, 1);
}